// round 1
// baseline (speedup 1.0000x reference)
#include <cuda_runtime.h>
#include <cstdint>

#define E       256
#define MDIM    512
#define NTOK    50000
#define DDIM    256
#define HEADS   8
#define DH      64
#define INNER   512
#define CHUNK   1024
#define NCHUNK  49          // 49*1024 = 50176 >= 50000
#define NSTEPS  16          // inner steps of 64 tokens
#define ISTEP   64
#define MB_W    1568        // mask bitword stride per row (>= ceil(50000/32)=1563)

// ---------------- scratch (device globals; no allocs allowed) ----------------
__device__ float    g_q   [E * INNER];                         // pre-scaled by dh^-0.5
__device__ float    g_kv  [51200000];                          // (NTOK, 1024): [k | v]
__device__ uint32_t g_mbits[E * MB_W];
__device__ int      g_mask_mode;
__device__ float    g_pnum[HEADS * NCHUNK * E * DH];           // 25.7 MB partial numerators
__device__ float    g_pden[HEADS * NCHUNK * E];
__device__ float    g_att [E * INNER];
__device__ float    g_t1  [E * MDIM];
__device__ float    g_m   [E * MDIM];
__device__ float    g_f1  [E * 4 * MDIM];
__device__ float    g_f2  [E * MDIM];

// ---------------- helpers ----------------
__device__ __forceinline__ uint32_t f2tf(float x) {
    uint32_t r;
    asm("cvt.rna.tf32.f32 %0, %1;" : "=r"(r) : "f"(x));
    return r;
}

__device__ __forceinline__ void mma8(float (&c)[4], const uint32_t (&a)[4],
                                     uint32_t b0, uint32_t b1) {
    asm volatile(
        "mma.sync.aligned.m16n8k8.row.col.f32.tf32.tf32.f32 "
        "{%0,%1,%2,%3},{%4,%5,%6,%7},{%8,%9},{%0,%1,%2,%3};"
        : "+f"(c[0]), "+f"(c[1]), "+f"(c[2]), "+f"(c[3])
        : "r"(a[0]), "r"(a[1]), "r"(a[2]), "r"(a[3]), "r"(b0), "r"(b1));
}

// ---------------- mask dtype sniffer ----------------
// classify first 256 32-bit words:
//   f32 (0/1.0f) words: {0, 0x3F800000}; i32: {0,1}
//   bf16 pairs: {0, 0x3F80, 0x3F800000, 0x3F803F80}
//   f64 hi-words: 0x3FF00000
//   bool bytes: words composed of bytes in {0,1} (e.g. 0x01010101)
// modes: 0 = 32-bit nonzero, 1 = byte nonzero, 2 = half nonzero, 3 = f64 nonzero
__global__ void detect_mask_kernel(const uint32_t* __restrict__ m) {
    int t = threadIdx.x;
    bool bf = false, by = false, d64 = false;
    for (int i = t; i < 256; i += 32) {
        uint32_t w = m[i];
        if (w == 0x3F803F80u || w == 0x00003F80u) bf = true;
        else if (w == 0x3FF00000u) d64 = true;
        else if (w != 0u && w != 1u && w != 0x3F800000u) by = true;
    }
    bf  = __any_sync(0xFFFFFFFFu, bf);
    by  = __any_sync(0xFFFFFFFFu, by);
    d64 = __any_sync(0xFFFFFFFFu, d64);
    if (t == 0) g_mask_mode = bf ? 2 : (d64 ? 3 : (by ? 1 : 0));
}

// pack mask (1,E,NTOK) into bitwords; bits beyond NTOK are 0
__global__ void mask_bits_kernel(const void* __restrict__ mask) {
    int w = blockIdx.x * blockDim.x + threadIdx.x;
    int r = blockIdx.y;
    if (w >= MB_W) return;
    uint32_t bits = 0;
    int n0 = w << 5;
    int mode = g_mask_mode;
    size_t base = (size_t)r * NTOK;
    if (n0 + 32 <= NTOK) {
        if (mode == 1) {
            const uint32_t* p = (const uint32_t*)((const uint8_t*)mask + base + n0);
            #pragma unroll
            for (int k = 0; k < 8; k++) {
                uint32_t u = p[k];
                #pragma unroll
                for (int b = 0; b < 4; b++)
                    bits |= (((u >> (8 * b)) & 0xFFu) ? 1u : 0u) << (k * 4 + b);
            }
        } else if (mode == 2) {
            const uint32_t* p = (const uint32_t*)((const uint16_t*)mask + base + n0);
            #pragma unroll
            for (int k = 0; k < 16; k++) {
                uint32_t u = p[k];
                bits |= ((u & 0xFFFFu) ? 1u : 0u) << (k * 2);
                bits |= ((u >> 16) ? 1u : 0u) << (k * 2 + 1);
            }
        } else if (mode == 3) {
            const uint2* p = (const uint2*)mask + base + n0;
            #pragma unroll
            for (int k = 0; k < 32; k++) {
                uint2 u = p[k];
                bits |= ((u.x | u.y) ? 1u : 0u) << k;
            }
        } else {
            const uint32_t* p = (const uint32_t*)mask + base + n0;
            #pragma unroll
            for (int k = 0; k < 32; k++)
                bits |= (p[k] ? 1u : 0u) << k;
        }
    } else {
        for (int b = 0; b < 32; b++) {
            int nn = n0 + b;
            if (nn >= NTOK) break;
            uint32_t v;
            if (mode == 1)      v = ((const uint8_t*)mask)[base + nn];
            else if (mode == 2) v = ((const uint16_t*)mask)[base + nn];
            else if (mode == 3) { uint2 u = ((const uint2*)mask)[base + nn]; v = u.x | u.y; }
            else                v = ((const uint32_t*)mask)[base + nn];
            bits |= (v ? 1u : 0u) << b;
        }
    }
    g_mbits[r * MB_W + w] = bits;
}

// ---------------- generic tf32 GEMM: C = act(alpha*A@B^T + bias) ----------------
// A (Md,Kd) row-major, B (Nd,Kd) row-major. BM=128 BN=64 BK=32, 256 threads.
// Nd % 64 == 0, Kd % 32 == 0 required; Md guarded.
template <int ACT>
__global__ void __launch_bounds__(256)
gemm_tf32(const float* __restrict__ A, const float* __restrict__ B,
          const float* __restrict__ bias, float* __restrict__ C,
          int Md, int Nd, int Kd, float alpha) {
    __shared__ float As[128][36];
    __shared__ float Bs[64][36];
    int bm = blockIdx.y * 128, bn = blockIdx.x * 64;
    int tid = threadIdx.x, warp = tid >> 5, lane = tid & 31;
    int wm = (warp >> 1) * 32, wn = (warp & 1) * 32;
    int g = lane >> 2, j = lane & 3;
    float acc[2][4][4] = {};

    for (int k0 = 0; k0 < Kd; k0 += 32) {
        __syncthreads();
        #pragma unroll
        for (int i = tid; i < 1024; i += 256) {           // A: 128x32 = 1024 float4
            int r = i >> 3, c4 = i & 7;
            float4 v = make_float4(0.f, 0.f, 0.f, 0.f);
            int gr = bm + r;
            if (gr < Md) v = *(const float4*)&A[(size_t)gr * Kd + k0 + c4 * 4];
            *(float4*)&As[r][c4 * 4] = v;
        }
        #pragma unroll
        for (int i = tid; i < 512; i += 256) {            // B: 64x32 = 512 float4
            int r = i >> 3, c4 = i & 7;
            float4 v = make_float4(0.f, 0.f, 0.f, 0.f);
            int gr = bn + r;
            if (gr < Nd) v = *(const float4*)&B[(size_t)gr * Kd + k0 + c4 * 4];
            *(float4*)&Bs[r][c4 * 4] = v;
        }
        __syncthreads();
        #pragma unroll
        for (int kk = 0; kk < 32; kk += 8) {
            uint32_t a[2][4], b[4][2];
            #pragma unroll
            for (int mi = 0; mi < 2; mi++) {
                int r = wm + mi * 16 + g;
                a[mi][0] = f2tf(As[r][kk + j]);
                a[mi][1] = f2tf(As[r + 8][kk + j]);
                a[mi][2] = f2tf(As[r][kk + 4 + j]);
                a[mi][3] = f2tf(As[r + 8][kk + 4 + j]);
            }
            #pragma unroll
            for (int ni = 0; ni < 4; ni++) {
                int cb = wn + ni * 8 + g;
                b[ni][0] = f2tf(Bs[cb][kk + j]);
                b[ni][1] = f2tf(Bs[cb][kk + 4 + j]);
            }
            #pragma unroll
            for (int mi = 0; mi < 2; mi++)
                #pragma unroll
                for (int ni = 0; ni < 4; ni++)
                    mma8(acc[mi][ni], a[mi], b[ni][0], b[ni][1]);
        }
    }
    #pragma unroll
    for (int mi = 0; mi < 2; mi++)
        #pragma unroll
        for (int ni = 0; ni < 4; ni++)
            #pragma unroll
            for (int q = 0; q < 4; q++) {
                int r  = bm + wm + mi * 16 + g + ((q >= 2) ? 8 : 0);
                int cc = bn + wn + ni * 8 + 2 * j + (q & 1);
                if (r < Md) {
                    float v = acc[mi][ni][q] * alpha + (bias ? bias[cc] : 0.f);
                    if (ACT) v = fmaxf(v, 0.f);
                    C[(size_t)r * Nd + cc] = v;
                }
            }
}

// ---------------- attention: partial (num, den) per (head, 1024-chunk) ----------------
// grid (NCHUNK, HEADS), 256 threads. Non-stabilized softmax (sim ~ N(0,1), safe).
#define ATTN_SMEM (107520)
__global__ void __launch_bounds__(256, 1) attn_kernel() {
    extern __shared__ float sm[];
    float*    qs = sm;                       // [256][68]
    float*    ks = qs + 256 * 68;            // [64][68]
    float*    vs = ks + 64 * 68;             // [64][72]
    uint32_t* mw = (uint32_t*)(vs + 64 * 72);// [256][2]

    int c = blockIdx.x, h = blockIdx.y;
    int tid = threadIdx.x, warp = tid >> 5, lane = tid & 31;
    int g = lane >> 2, j = lane & 3;
    int row0 = warp * 32;

    // load q tile (E x DH) for this head
    #pragma unroll
    for (int i = tid; i < 4096; i += 256) {
        int row = i >> 4, c4 = i & 15;
        float4 v = *(const float4*)&g_q[row * INNER + h * DH + (c4 << 2)];
        *(float4*)&qs[row * 68 + (c4 << 2)] = v;
    }

    float acc[2][8][4] = {};
    float den[2][2] = {};

    #pragma unroll 1
    for (int s = 0; s < NSTEPS; s++) {
        int n0 = c * CHUNK + s * ISTEP;
        __syncthreads();
        // K/V subtile: 64 tokens x 64 dims, OOB -> 0
        #pragma unroll
        for (int i = tid; i < 1024; i += 256) {
            int r = i >> 4, c4 = i & 15;
            int nidx = n0 + r;
            float4 kv4 = make_float4(0.f, 0.f, 0.f, 0.f);
            float4 vv4 = make_float4(0.f, 0.f, 0.f, 0.f);
            if (nidx < NTOK) {
                size_t rb = (size_t)nidx * 1024;
                kv4 = *(const float4*)&g_kv[rb + h * DH + (c4 << 2)];
                vv4 = *(const float4*)&g_kv[rb + 512 + h * DH + (c4 << 2)];
            }
            *(float4*)&ks[r * 68 + (c4 << 2)] = kv4;
            *(float4*)&vs[r * 72 + (c4 << 2)] = vv4;
        }
        {   // mask words for this 64-token window: 2 per query row
            int w0 = n0 >> 5;
            #pragma unroll
            for (int i = tid; i < 512; i += 256)
                mw[i] = g_mbits[(i >> 1) * MB_W + w0 + (i & 1)];
        }
        __syncthreads();

        // ---- QK^T : S[2][8][4], q pre-scaled by dh^-0.5 ----
        float S[2][8][4] = {};
        #pragma unroll
        for (int kk = 0; kk < 64; kk += 8) {
            uint32_t a[2][4];
            #pragma unroll
            for (int mi = 0; mi < 2; mi++) {
                int r = row0 + mi * 16 + g;
                a[mi][0] = f2tf(qs[r * 68 + kk + j]);
                a[mi][1] = f2tf(qs[(r + 8) * 68 + kk + j]);
                a[mi][2] = f2tf(qs[r * 68 + kk + 4 + j]);
                a[mi][3] = f2tf(qs[(r + 8) * 68 + kk + 4 + j]);
            }
            #pragma unroll
            for (int ni = 0; ni < 8; ni++) {
                int kr = ni * 8 + g;
                uint32_t b0 = f2tf(ks[kr * 68 + kk + j]);
                uint32_t b1 = f2tf(ks[kr * 68 + kk + 4 + j]);
                mma8(S[0][ni], a[0], b0, b1);
                mma8(S[1][ni], a[1], b0, b1);
            }
        }

        // ---- mask + exp -> P (in S), accumulate den ----
        uint32_t mk[2][2][2];
        #pragma unroll
        for (int mi = 0; mi < 2; mi++)
            #pragma unroll
            for (int rh = 0; rh < 2; rh++) {
                int r = row0 + mi * 16 + rh * 8 + g;
                mk[mi][rh][0] = mw[r * 2];
                mk[mi][rh][1] = mw[r * 2 + 1];
            }
        #pragma unroll
        for (int ni = 0; ni < 8; ni++)
            #pragma unroll
            for (int mi = 0; mi < 2; mi++)
                #pragma unroll
                for (int q = 0; q < 4; q++) {
                    int rh = q >> 1;
                    int colL = ni * 8 + 2 * j + (q & 1);
                    uint32_t wv = mk[mi][rh][ni >> 2];
                    bool keep = (wv >> (colL & 31)) & 1u;
                    float p = keep ? __expf(S[mi][ni][q]) : 0.f;
                    S[mi][ni][q] = p;
                    den[mi][rh] += p;
                }

        // ---- P @ V ----
        #pragma unroll
        for (int kt = 0; kt < 8; kt++) {
            uint32_t a[2][4];
            #pragma unroll
            for (int mi = 0; mi < 2; mi++) {
                int qb = lane & ~3;
                int s0 = qb | (j >> 1);
                int s1 = qb | (2 + (j >> 1));
                float t0, t1;
                t0 = __shfl_sync(0xFFFFFFFFu, S[mi][kt][0], s0);
                t1 = __shfl_sync(0xFFFFFFFFu, S[mi][kt][1], s0);
                float f0 = (j & 1) ? t1 : t0;
                t0 = __shfl_sync(0xFFFFFFFFu, S[mi][kt][2], s0);
                t1 = __shfl_sync(0xFFFFFFFFu, S[mi][kt][3], s0);
                float f1 = (j & 1) ? t1 : t0;
                t0 = __shfl_sync(0xFFFFFFFFu, S[mi][kt][0], s1);
                t1 = __shfl_sync(0xFFFFFFFFu, S[mi][kt][1], s1);
                float f2 = (j & 1) ? t1 : t0;
                t0 = __shfl_sync(0xFFFFFFFFu, S[mi][kt][2], s1);
                t1 = __shfl_sync(0xFFFFFFFFu, S[mi][kt][3], s1);
                float f3 = (j & 1) ? t1 : t0;
                a[mi][0] = f2tf(f0); a[mi][1] = f2tf(f1);
                a[mi][2] = f2tf(f2); a[mi][3] = f2tf(f3);
            }
            #pragma unroll
            for (int nj = 0; nj < 8; nj++) {
                uint32_t b0 = f2tf(vs[(kt * 8 + j) * 72 + nj * 8 + g]);
                uint32_t b1 = f2tf(vs[(kt * 8 + 4 + j) * 72 + nj * 8 + g]);
                mma8(acc[0][nj], a[0], b0, b1);
                mma8(acc[1][nj], a[1], b0, b1);
            }
        }
    }

    // ---- write partials ----
    size_t base = (size_t)(h * NCHUNK + c) * E;
    #pragma unroll
    for (int mi = 0; mi < 2; mi++)
        #pragma unroll
        for (int rh = 0; rh < 2; rh++) {
            float dsum = den[mi][rh];
            dsum += __shfl_xor_sync(0xFFFFFFFFu, dsum, 1);
            dsum += __shfl_xor_sync(0xFFFFFFFFu, dsum, 2);
            int r = row0 + mi * 16 + rh * 8 + g;
            if (j == 0) g_pden[base + r] = dsum;
        }
    #pragma unroll
    for (int mi = 0; mi < 2; mi++)
        #pragma unroll
        for (int nj = 0; nj < 8; nj++)
            #pragma unroll
            for (int q = 0; q < 4; q++) {
                int r = row0 + mi * 16 + g + ((q >= 2) ? 8 : 0);
                int col = nj * 8 + 2 * j + (q & 1);
                g_pnum[(base + r) * DH + col] = acc[mi][nj][q];
            }
}

// ---------------- combine partials: att = num/den ----------------
__global__ void combine_kernel() {
    int idx = blockIdx.x * 256 + threadIdx.x;    // 131072 total
    int i = idx >> 9, col = idx & 511;
    int h = col >> 6, t = col & 63;
    float num = 0.f, dsum = 0.f;
    #pragma unroll 7
    for (int c = 0; c < NCHUNK; c++) {
        size_t base = (size_t)(h * NCHUNK + c) * E + i;
        num  += g_pnum[base * DH + t];
        dsum += g_pden[base];
    }
    g_att[i * INNER + col] = num / dsum;
}

// ---------------- residual + LayerNorm over 512 cols ----------------
__global__ void ln_kernel(const float* __restrict__ X, const float* __restrict__ R,
                          float* __restrict__ out) {
    int row = blockIdx.x, tid = threadIdx.x;     // 128 threads
    __shared__ float sh1[4], sh2[4];
    float4 x = ((const float4*)X)[row * 128 + tid];
    float4 rr = ((const float4*)R)[row * 128 + tid];
    float v0 = x.x + rr.x, v1 = x.y + rr.y, v2 = x.z + rr.z, v3 = x.w + rr.w;
    float s = v0 + v1 + v2 + v3;
    #pragma unroll
    for (int o = 16; o; o >>= 1) s += __shfl_xor_sync(0xFFFFFFFFu, s, o);
    if ((tid & 31) == 0) sh1[tid >> 5] = s;
    __syncthreads();
    float mu = (sh1[0] + sh1[1] + sh1[2] + sh1[3]) * (1.f / 512.f);
    float d0 = v0 - mu, d1 = v1 - mu, d2 = v2 - mu, d3 = v3 - mu;
    float ss = d0 * d0 + d1 * d1 + d2 * d2 + d3 * d3;
    #pragma unroll
    for (int o = 16; o; o >>= 1) ss += __shfl_xor_sync(0xFFFFFFFFu, ss, o);
    if ((tid & 31) == 0) sh2[tid >> 5] = ss;
    __syncthreads();
    float var = (sh2[0] + sh2[1] + sh2[2] + sh2[3]) * (1.f / 512.f);
    float inv = rsqrtf(var + 1e-5f);
    float4 o4 = make_float4(d0 * inv, d1 * inv, d2 * inv, d3 * inv);
    ((float4*)out)[row * 128 + tid] = o4;
}

// ---------------- launcher ----------------
extern "C" void kernel_launch(void* const* d_in, const int* in_sizes, int n_in,
                              void* d_out, int out_size) {
    const float* M    = (const float*)d_in[0];
    const float* x    = (const float*)d_in[1];
    const void*  mask = d_in[2];
    const float* Wq   = (const float*)d_in[3];
    const float* Wkv  = (const float*)d_in[4];
    const float* bkv  = (const float*)d_in[5];
    const float* Wo   = (const float*)d_in[6];
    const float* bo   = (const float*)d_in[7];
    const float* W1   = (const float*)d_in[8];
    const float* b1   = (const float*)d_in[9];
    const float* W2   = (const float*)d_in[10];
    const float* b2   = (const float*)d_in[11];
    float* out = (float*)d_out;

    float *pq, *pkv, *patt, *pt1, *pm, *pf1, *pf2;
    cudaGetSymbolAddress((void**)&pq,   g_q);
    cudaGetSymbolAddress((void**)&pkv,  g_kv);
    cudaGetSymbolAddress((void**)&patt, g_att);
    cudaGetSymbolAddress((void**)&pt1,  g_t1);
    cudaGetSymbolAddress((void**)&pm,   g_m);
    cudaGetSymbolAddress((void**)&pf1,  g_f1);
    cudaGetSymbolAddress((void**)&pf2,  g_f2);

    cudaFuncSetAttribute(attn_kernel, cudaFuncAttributeMaxDynamicSharedMemorySize, ATTN_SMEM);

    detect_mask_kernel<<<1, 32>>>((const uint32_t*)mask);
    mask_bits_kernel<<<dim3(7, E), 256>>>(mask);

    // q = (M @ Wq^T) * dh^-0.5
    gemm_tf32<0><<<dim3(8, 2), 256>>>(M, Wq, nullptr, pq, E, INNER, MDIM, 0.125f);
    // kv = x @ Wkv^T + bkv
    gemm_tf32<0><<<dim3(16, 391), 256>>>(x, Wkv, bkv, pkv, NTOK, 1024, DDIM, 1.f);

    attn_kernel<<<dim3(NCHUNK, HEADS), 256, ATTN_SMEM>>>();
    combine_kernel<<<512, 256>>>();

    // out = att @ Wo^T + bo ; m = LN(out + M)
    gemm_tf32<0><<<dim3(8, 2), 256>>>(patt, Wo, bo, pt1, E, MDIM, INNER, 1.f);
    ln_kernel<<<E, 128>>>(pt1, M, pm);
    // ffn = relu(m @ W1^T + b1) @ W2^T + b2 ; z = LN(ffn + m)
    gemm_tf32<1><<<dim3(32, 2), 256>>>(pm, W1, b1, pf1, E, 4 * MDIM, MDIM, 1.f);
    gemm_tf32<0><<<dim3(8, 2), 256>>>(pf1, W2, b2, pf2, E, MDIM, 4 * MDIM, 1.f);
    ln_kernel<<<E, 128>>>(pf2, pm, out);
}

// round 3
// speedup vs baseline: 1.0377x; 1.0377x over previous
#include <cuda_runtime.h>
#include <cstdint>

#define E       256
#define MDIM    512
#define NTOK    50000
#define DDIM    256
#define HEADS   8
#define DH      64
#define INNER   512
#define CHUNK   1024
#define NCHUNK  49          // 49*1024 = 50176 >= 50000
#define NSTEPS  16          // inner steps of 64 tokens
#define ISTEP   64
#define MB_W    1568        // mask bitword stride per row (>= ceil(50000/32)=1563)

// ---------------- scratch (device globals; no allocs allowed) ----------------
__device__ float    g_q   [E * INNER];                         // pre-scaled by dh^-0.5
__device__ float    g_kv  [51200000];                          // (NTOK, 1024): [k | v]
__device__ uint32_t g_mbits[E * MB_W];
__device__ int      g_mask_mode;
__device__ float    g_pnum[HEADS * NCHUNK * E * DH];
__device__ float    g_pden[HEADS * NCHUNK * E];
__device__ float    g_att [E * INNER];
__device__ float    g_t1  [E * MDIM];
__device__ float    g_m   [E * MDIM];
__device__ float    g_f1  [E * 4 * MDIM];
__device__ float    g_f2  [E * MDIM];

// ---------------- helpers ----------------
__device__ __forceinline__ uint32_t f2tf(float x) {
    uint32_t r;
    asm("cvt.rna.tf32.f32 %0, %1;" : "=r"(r) : "f"(x));
    return r;
}

__device__ __forceinline__ void mma8(float (&c)[4], const uint32_t (&a)[4],
                                     uint32_t b0, uint32_t b1) {
    asm volatile(
        "mma.sync.aligned.m16n8k8.row.col.f32.tf32.tf32.f32 "
        "{%0,%1,%2,%3},{%4,%5,%6,%7},{%8,%9},{%0,%1,%2,%3};"
        : "+f"(c[0]), "+f"(c[1]), "+f"(c[2]), "+f"(c[3])
        : "r"(a[0]), "r"(a[1]), "r"(a[2]), "r"(a[3]), "r"(b0), "r"(b1));
}

// ---------------- mask dtype sniffer (unchanged, proven) ----------------
__global__ void detect_mask_kernel(const uint32_t* __restrict__ m) {
    int t = threadIdx.x;
    bool bf = false, by = false, d64 = false;
    for (int i = t; i < 256; i += 32) {
        uint32_t w = m[i];
        if (w == 0x3F803F80u || w == 0x00003F80u) bf = true;
        else if (w == 0x3FF00000u) d64 = true;
        else if (w != 0u && w != 1u && w != 0x3F800000u) by = true;
    }
    bf  = __any_sync(0xFFFFFFFFu, bf);
    by  = __any_sync(0xFFFFFFFFu, by);
    d64 = __any_sync(0xFFFFFFFFu, d64);
    if (t == 0) g_mask_mode = bf ? 2 : (d64 ? 3 : (by ? 1 : 0));
}

__global__ void mask_bits_kernel(const void* __restrict__ mask) {
    int w = blockIdx.x * blockDim.x + threadIdx.x;
    int r = blockIdx.y;
    if (w >= MB_W) return;
    uint32_t bits = 0;
    int n0 = w << 5;
    int mode = g_mask_mode;
    size_t base = (size_t)r * NTOK;
    if (n0 + 32 <= NTOK) {
        if (mode == 1) {
            const uint32_t* p = (const uint32_t*)((const uint8_t*)mask + base + n0);
            #pragma unroll
            for (int k = 0; k < 8; k++) {
                uint32_t u = p[k];
                #pragma unroll
                for (int b = 0; b < 4; b++)
                    bits |= (((u >> (8 * b)) & 0xFFu) ? 1u : 0u) << (k * 4 + b);
            }
        } else if (mode == 2) {
            const uint32_t* p = (const uint32_t*)((const uint16_t*)mask + base + n0);
            #pragma unroll
            for (int k = 0; k < 16; k++) {
                uint32_t u = p[k];
                bits |= ((u & 0xFFFFu) ? 1u : 0u) << (k * 2);
                bits |= ((u >> 16) ? 1u : 0u) << (k * 2 + 1);
            }
        } else if (mode == 3) {
            const uint2* p = (const uint2*)mask + base + n0;
            #pragma unroll
            for (int k = 0; k < 32; k++) {
                uint2 u = p[k];
                bits |= ((u.x | u.y) ? 1u : 0u) << k;
            }
        } else {
            const uint32_t* p = (const uint32_t*)mask + base + n0;
            #pragma unroll
            for (int k = 0; k < 32; k++)
                bits |= (p[k] ? 1u : 0u) << k;
        }
    } else {
        for (int b = 0; b < 32; b++) {
            int nn = n0 + b;
            if (nn >= NTOK) break;
            uint32_t v;
            if (mode == 1)      v = ((const uint8_t*)mask)[base + nn];
            else if (mode == 2) v = ((const uint16_t*)mask)[base + nn];
            else if (mode == 3) { uint2 u = ((const uint2*)mask)[base + nn]; v = u.x | u.y; }
            else                v = ((const uint32_t*)mask)[base + nn];
            bits |= (v ? 1u : 0u) << b;
        }
    }
    g_mbits[r * MB_W + w] = bits;
}

// ================= tf32 GEMM: C = act(alpha*A@B^T + bias) =================
// A (Md,Kd) row-major, B (Nd,Kd) row-major. BM=128 BN=256 BK=32, 256 thr,
// 8 warps = 2(m) x 4(n), warp tile 64x64. Fragment-packed tf32 smem,
// double-buffered with register-staged global prefetch.
// Requires: Nd % 256 == 0, Kd % 32 == 0. Md guarded.
#define GEMM_SMEM (24576 * 4)
template <int ACT>
__global__ void __launch_bounds__(256, 1)
gemm_tf32(const float* __restrict__ A, const float* __restrict__ B,
          const float* __restrict__ bias, float* __restrict__ C,
          int Md, int Nd, int Kd, float alpha) {
    extern __shared__ uint32_t smg[];
    uint32_t* Ap = smg;           // 2 stages x 4096 (rb8 x kb4 x 32 x 4)
    uint32_t* Bp = smg + 8192;    // 2 stages x 8192 (nb32 x kb4 x 32 x 2)
    int bm = blockIdx.y * 128, bn = blockIdx.x * 256;
    int tid = threadIdx.x, warp = tid >> 5, lane = tid & 31;
    int g = lane >> 2, j = lane & 3;
    int wm = warp >> 2, wn = warp & 3;

    float4 aR[4], bR[8];
    auto ldg = [&](int kt) {
        int k0 = kt * 32;
        #pragma unroll
        for (int p = 0; p < 4; p++) {
            int idx = p * 256 + tid, r = idx >> 3, c4 = idx & 7;
            int gr = bm + r;
            aR[p] = (gr < Md) ? *(const float4*)&A[(size_t)gr * Kd + k0 + c4 * 4]
                              : make_float4(0.f, 0.f, 0.f, 0.f);
        }
        #pragma unroll
        for (int p = 0; p < 8; p++) {
            int idx = p * 256 + tid, r = idx >> 3, c4 = idx & 7;
            bR[p] = *(const float4*)&B[(size_t)(bn + r) * Kd + k0 + c4 * 4];
        }
    };
    auto sts = [&](int buf) {
        uint32_t* Ad = Ap + buf * 4096;
        uint32_t* Bd = Bp + buf * 8192;
        #pragma unroll
        for (int p = 0; p < 4; p++) {
            int idx = p * 256 + tid, r = idx >> 3, cc = (idx & 7) * 4;
            int rb = r >> 4, rr = r & 15, hh = rr >> 3, gg = rr & 7;
            int kb = cc >> 3, vv = (cc & 7) >> 2;
            uint32_t base = (uint32_t)(((rb * 4 + kb) * 32 + gg * 4) * 4 + (hh + 2 * vv));
            Ad[base + 0]  = f2tf(aR[p].x);
            Ad[base + 4]  = f2tf(aR[p].y);
            Ad[base + 8]  = f2tf(aR[p].z);
            Ad[base + 12] = f2tf(aR[p].w);
        }
        #pragma unroll
        for (int p = 0; p < 8; p++) {
            int idx = p * 256 + tid, r = idx >> 3, cc = (idx & 7) * 4;
            int nb = r >> 3, gg = r & 7, kb = cc >> 3, s = (cc & 7) >> 2;
            uint32_t base = (uint32_t)(((nb * 4 + kb) * 32 + gg * 4) * 2 + s);
            Bd[base + 0] = f2tf(bR[p].x);
            Bd[base + 2] = f2tf(bR[p].y);
            Bd[base + 4] = f2tf(bR[p].z);
            Bd[base + 6] = f2tf(bR[p].w);
        }
    };

    float acc[4][8][4] = {};
    int nt = Kd >> 5;
    ldg(0); sts(0); __syncthreads();
    for (int kt = 0; kt < nt; kt++) {
        if (kt + 1 < nt) ldg(kt + 1);
        const uint32_t* Ab = Ap + (kt & 1) * 4096;
        const uint32_t* Bb = Bp + (kt & 1) * 8192;
        #pragma unroll
        for (int kb = 0; kb < 4; kb++) {
            uint32_t a[4][4];
            #pragma unroll
            for (int mi = 0; mi < 4; mi++) {
                uint4 av = *(const uint4*)&Ab[(((wm * 4 + mi) * 4 + kb) * 32 + lane) * 4];
                a[mi][0] = av.x; a[mi][1] = av.y; a[mi][2] = av.z; a[mi][3] = av.w;
            }
            #pragma unroll
            for (int ni = 0; ni < 8; ni++) {
                uint2 b = *(const uint2*)&Bb[(((wn * 8 + ni) * 4 + kb) * 32 + lane) * 2];
                #pragma unroll
                for (int mi = 0; mi < 4; mi++)
                    mma8(acc[mi][ni], a[mi], b.x, b.y);
            }
        }
        if (kt + 1 < nt) { sts((kt + 1) & 1); __syncthreads(); }
    }
    #pragma unroll
    for (int mi = 0; mi < 4; mi++)
        #pragma unroll
        for (int ni = 0; ni < 8; ni++)
            #pragma unroll
            for (int rh = 0; rh < 2; rh++) {
                int r = bm + wm * 64 + mi * 16 + rh * 8 + g;
                if (r < Md) {
                    int cb = bn + wn * 64 + ni * 8 + 2 * j;
                    float v0 = acc[mi][ni][rh * 2 + 0] * alpha + (bias ? bias[cb] : 0.f);
                    float v1 = acc[mi][ni][rh * 2 + 1] * alpha + (bias ? bias[cb + 1] : 0.f);
                    if (ACT) { v0 = fmaxf(v0, 0.f); v1 = fmaxf(v1, 0.f); }
                    *(float2*)&C[(size_t)r * Nd + cb] = make_float2(v0, v1);
                }
            }
}

// ================= attention: partial (num, den) per (head, chunk) =========
// 256 threads = 8 warps x 32 query rows. Fragment-packed tf32 q/K, sigma-
// permuted V so exp(S) C-fragments ARE the P@V A-fragments (no shuffles).
// Non-stabilized softmax (sim ~ N(0,1) -> exp fp32-safe; masked -> p=0).
#define ATTN_SMEM (33792 * 4)
__global__ void __launch_bounds__(256, 1) attn_kernel() {
    extern __shared__ uint32_t smu[];
    uint32_t* qp  = smu;            // 16384 : rb16 x kk8 x 32 x 4
    uint32_t* kp  = smu + 16384;    // 2 x 4096 : nb8 x kk8 x 32 x 2
    uint32_t* vp  = smu + 24576;    // 2 x 4096 : nb8 x kt8 x 32 x 2 (sigma-permuted rows)
    uint32_t* mwp = smu + 32768;    // 2 x 512

    int c = blockIdx.x, h = blockIdx.y;
    int tid = threadIdx.x, warp = tid >> 5, lane = tid & 31;
    int g = lane >> 2, j = lane & 3;
    int row0 = warp * 32;

    // ---- q tile load + A-pack (once). 256 rows x 16 float4 = 4096 float4. ----
    #pragma unroll
    for (int p = 0; p < 16; p++) {                 // FIX R2: was p < 4 (only rows 0..63 packed)
        int idx = p * 256 + tid, r = idx >> 4, cc = (idx & 15) * 4;
        float4 v = *(const float4*)&g_q[r * INNER + h * DH + cc];
        int rb = r >> 4, rr = r & 15, hh = rr >> 3, gg = rr & 7;
        int kb = cc >> 3, vv = (cc & 7) >> 2;
        uint32_t base = (uint32_t)(((rb * 8 + kb) * 32 + gg * 4) * 4 + (hh + 2 * vv));
        qp[base + 0]  = f2tf(v.x);
        qp[base + 4]  = f2tf(v.y);
        qp[base + 8]  = f2tf(v.z);
        qp[base + 12] = f2tf(v.w);
    }

    float4 kR[4], vR[4];
    uint32_t mR[2];
    auto ldg_tile = [&](int s) {
        int n0 = c * CHUNK + s * ISTEP;
        #pragma unroll
        for (int p = 0; p < 4; p++) {
            int idx = p * 256 + tid, tok = idx >> 4, f4 = idx & 15;
            int nidx = n0 + tok;
            if (nidx < NTOK) {
                size_t rb = (size_t)nidx * 1024 + h * DH + f4 * 4;
                kR[p] = *(const float4*)&g_kv[rb];
                vR[p] = *(const float4*)&g_kv[rb + 512];
            } else {
                kR[p] = make_float4(0.f, 0.f, 0.f, 0.f);
                vR[p] = kR[p];
            }
        }
        int w0 = n0 >> 5;
        mR[0] = g_mbits[(tid >> 1) * MB_W + w0 + (tid & 1)];
        int t2 = tid + 256;
        mR[1] = g_mbits[(t2 >> 1) * MB_W + w0 + (t2 & 1)];
    };
    auto sts_tile = [&](int buf) {
        uint32_t* kd = kp + buf * 4096;
        uint32_t* vd = vp + buf * 4096;
        #pragma unroll
        for (int p = 0; p < 4; p++) {
            int idx = p * 256 + tid, tok = idx >> 4, cc = (idx & 15) * 4;
            // K: B-pack (n = token, k = dh)
            int nb = tok >> 3, gg = tok & 7, kb = cc >> 3, s = (cc & 7) >> 2;
            uint32_t kbase = (uint32_t)(((nb * 8 + kb) * 32 + gg * 4) * 2 + s);
            kd[kbase + 0] = f2tf(kR[p].x);
            kd[kbase + 2] = f2tf(kR[p].y);
            kd[kbase + 4] = f2tf(kR[p].z);
            kd[kbase + 6] = f2tf(kR[p].w);
            // V: B-pack with sigma row permutation (n = dh, k = token)
            int kt = tok >> 3, w = tok & 7, jv = w >> 1, sv = w & 1;
            #pragma unroll
            for (int u = 0; u < 4; u++) {
                int d = cc + u, nbv = d >> 3, gv = d & 7;
                uint32_t a = (uint32_t)(((nbv * 8 + kt) * 32 + gv * 4 + jv) * 2 + sv);
                float val = (u == 0) ? vR[p].x : (u == 1) ? vR[p].y : (u == 2) ? vR[p].z : vR[p].w;
                vd[a] = f2tf(val);
            }
        }
        mwp[buf * 512 + tid]       = mR[0];
        mwp[buf * 512 + tid + 256] = mR[1];
    };

    float acc[2][8][4] = {};
    float den[2][2] = {};

    ldg_tile(0); sts_tile(0); __syncthreads();

    #pragma unroll 1
    for (int s = 0; s < NSTEPS; s++) {
        int buf = s & 1;
        const uint32_t* kb_ = kp + buf * 4096;
        const uint32_t* vb_ = vp + buf * 4096;
        const uint32_t* mwb = mwp + buf * 512;

        // ---- QK^T (q pre-scaled by dh^-0.5) ----
        float S[2][8][4] = {};
        int rb0 = warp * 2;
        #pragma unroll
        for (int kk = 0; kk < 8; kk++) {
            uint4 av0 = *(const uint4*)&qp[((rb0 * 8 + kk) * 32 + lane) * 4];
            uint4 av1 = *(const uint4*)&qp[(((rb0 + 1) * 8 + kk) * 32 + lane) * 4];
            uint32_t a0[4] = {av0.x, av0.y, av0.z, av0.w};
            uint32_t a1[4] = {av1.x, av1.y, av1.z, av1.w};
            #pragma unroll
            for (int ni = 0; ni < 8; ni++) {
                uint2 b = *(const uint2*)&kb_[((ni * 8 + kk) * 32 + lane) * 2];
                mma8(S[0][ni], a0, b.x, b.y);
                mma8(S[1][ni], a1, b.x, b.y);
            }
        }

        // ---- mask + exp -> tf32 P (C-frag layout) ----
        uint32_t Pu[2][8][4];
        #pragma unroll
        for (int mi = 0; mi < 2; mi++) {
            uint32_t m0a = mwb[(row0 + mi * 16 + g) * 2];
            uint32_t m0b = mwb[(row0 + mi * 16 + g) * 2 + 1];
            uint32_t m1a = mwb[(row0 + mi * 16 + 8 + g) * 2];
            uint32_t m1b = mwb[(row0 + mi * 16 + 8 + g) * 2 + 1];
            #pragma unroll
            for (int ni = 0; ni < 8; ni++) {
                uint32_t wlo = (ni < 4) ? m0a : m0b;
                uint32_t whi = (ni < 4) ? m1a : m1b;
                #pragma unroll
                for (int q = 0; q < 4; q++) {
                    int colb = (ni * 8 + 2 * j + (q & 1)) & 31;
                    uint32_t wv = (q >> 1) ? whi : wlo;
                    float p = ((wv >> colb) & 1u) ? __expf(S[mi][ni][q]) : 0.f;
                    den[mi][q >> 1] += p;
                    Pu[mi][ni][q] = f2tf(p);
                }
            }
        }

        if (s + 1 < NSTEPS) ldg_tile(s + 1);

        // ---- P @ V : C-frag == A-frag under sigma (register rename only) ----
        #pragma unroll
        for (int kt = 0; kt < 8; kt++) {
            uint32_t a0[4] = {Pu[0][kt][0], Pu[0][kt][2], Pu[0][kt][1], Pu[0][kt][3]};
            uint32_t a1[4] = {Pu[1][kt][0], Pu[1][kt][2], Pu[1][kt][1], Pu[1][kt][3]};
            #pragma unroll
            for (int nj = 0; nj < 8; nj++) {
                uint2 b = *(const uint2*)&vb_[((nj * 8 + kt) * 32 + lane) * 2];
                mma8(acc[0][nj], a0, b.x, b.y);
                mma8(acc[1][nj], a1, b.x, b.y);
            }
        }

        if (s + 1 < NSTEPS) { sts_tile((s + 1) & 1); __syncthreads(); }
    }

    // ---- write partials ----
    size_t base = (size_t)(h * NCHUNK + c) * E;
    #pragma unroll
    for (int mi = 0; mi < 2; mi++)
        #pragma unroll
        for (int rh = 0; rh < 2; rh++) {
            float dsum = den[mi][rh];
            dsum += __shfl_xor_sync(0xFFFFFFFFu, dsum, 1);
            dsum += __shfl_xor_sync(0xFFFFFFFFu, dsum, 2);
            int r = row0 + mi * 16 + rh * 8 + g;
            if (j == 0) g_pden[base + r] = dsum;
        }
    #pragma unroll
    for (int mi = 0; mi < 2; mi++)
        #pragma unroll
        for (int nj = 0; nj < 8; nj++)
            #pragma unroll
            for (int q = 0; q < 4; q++) {
                int r = row0 + mi * 16 + g + ((q >= 2) ? 8 : 0);
                int col = nj * 8 + 2 * j + (q & 1);
                g_pnum[(base + r) * DH + col] = acc[mi][nj][q];
            }
}

// ---------------- combine partials: att = num/den ----------------
__global__ void combine_kernel() {
    int idx = blockIdx.x * 256 + threadIdx.x;    // 131072 total
    int i = idx >> 9, col = idx & 511;
    int h = col >> 6, t = col & 63;
    float num = 0.f, dsum = 0.f;
    #pragma unroll 7
    for (int c = 0; c < NCHUNK; c++) {
        size_t base = (size_t)(h * NCHUNK + c) * E + i;
        num  += g_pnum[base * DH + t];
        dsum += g_pden[base];
    }
    g_att[i * INNER + col] = num / dsum;
}

// ---------------- residual + LayerNorm over 512 cols ----------------
__global__ void ln_kernel(const float* __restrict__ X, const float* __restrict__ R,
                          float* __restrict__ out) {
    int row = blockIdx.x, tid = threadIdx.x;     // 128 threads
    __shared__ float sh1[4], sh2[4];
    float4 x = ((const float4*)X)[row * 128 + tid];
    float4 rr = ((const float4*)R)[row * 128 + tid];
    float v0 = x.x + rr.x, v1 = x.y + rr.y, v2 = x.z + rr.z, v3 = x.w + rr.w;
    float s = v0 + v1 + v2 + v3;
    #pragma unroll
    for (int o = 16; o; o >>= 1) s += __shfl_xor_sync(0xFFFFFFFFu, s, o);
    if ((tid & 31) == 0) sh1[tid >> 5] = s;
    __syncthreads();
    float mu = (sh1[0] + sh1[1] + sh1[2] + sh1[3]) * (1.f / 512.f);
    float d0 = v0 - mu, d1 = v1 - mu, d2 = v2 - mu, d3 = v3 - mu;
    float ss = d0 * d0 + d1 * d1 + d2 * d2 + d3 * d3;
    #pragma unroll
    for (int o = 16; o; o >>= 1) ss += __shfl_xor_sync(0xFFFFFFFFu, ss, o);
    if ((tid & 31) == 0) sh2[tid >> 5] = ss;
    __syncthreads();
    float var = (sh2[0] + sh2[1] + sh2[2] + sh2[3]) * (1.f / 512.f);
    float inv = rsqrtf(var + 1e-5f);
    float4 o4 = make_float4(d0 * inv, d1 * inv, d2 * inv, d3 * inv);
    ((float4*)out)[row * 128 + tid] = o4;
}

// ---------------- launcher ----------------
extern "C" void kernel_launch(void* const* d_in, const int* in_sizes, int n_in,
                              void* d_out, int out_size) {
    const float* M    = (const float*)d_in[0];
    const float* x    = (const float*)d_in[1];
    const void*  mask = d_in[2];
    const float* Wq   = (const float*)d_in[3];
    const float* Wkv  = (const float*)d_in[4];
    const float* bkv  = (const float*)d_in[5];
    const float* Wo   = (const float*)d_in[6];
    const float* bo   = (const float*)d_in[7];
    const float* W1   = (const float*)d_in[8];
    const float* b1   = (const float*)d_in[9];
    const float* W2   = (const float*)d_in[10];
    const float* b2   = (const float*)d_in[11];
    float* out = (float*)d_out;

    float *pq, *pkv, *patt, *pt1, *pm, *pf1, *pf2;
    cudaGetSymbolAddress((void**)&pq,   g_q);
    cudaGetSymbolAddress((void**)&pkv,  g_kv);
    cudaGetSymbolAddress((void**)&patt, g_att);
    cudaGetSymbolAddress((void**)&pt1,  g_t1);
    cudaGetSymbolAddress((void**)&pm,   g_m);
    cudaGetSymbolAddress((void**)&pf1,  g_f1);
    cudaGetSymbolAddress((void**)&pf2,  g_f2);

    cudaFuncSetAttribute(attn_kernel, cudaFuncAttributeMaxDynamicSharedMemorySize, ATTN_SMEM);
    cudaFuncSetAttribute(gemm_tf32<0>, cudaFuncAttributeMaxDynamicSharedMemorySize, GEMM_SMEM);
    cudaFuncSetAttribute(gemm_tf32<1>, cudaFuncAttributeMaxDynamicSharedMemorySize, GEMM_SMEM);

    detect_mask_kernel<<<1, 32>>>((const uint32_t*)mask);
    mask_bits_kernel<<<dim3(7, E), 256>>>(mask);

    // q = (M @ Wq^T) * dh^-0.5     (Md=256, Nd=512, Kd=512)
    gemm_tf32<0><<<dim3(2, 2), 256, GEMM_SMEM>>>(M, Wq, nullptr, pq, E, INNER, MDIM, 0.125f);
    // kv = x @ Wkv^T + bkv         (Md=50000, Nd=1024, Kd=256)
    gemm_tf32<0><<<dim3(4, 391), 256, GEMM_SMEM>>>(x, Wkv, bkv, pkv, NTOK, 1024, DDIM, 1.f);

    attn_kernel<<<dim3(NCHUNK, HEADS), 256, ATTN_SMEM>>>();
    combine_kernel<<<512, 256>>>();

    // out = att @ Wo^T + bo ; m = LN(out + M)
    gemm_tf32<0><<<dim3(2, 2), 256, GEMM_SMEM>>>(patt, Wo, bo, pt1, E, MDIM, INNER, 1.f);
    ln_kernel<<<E, 128>>>(pt1, M, pm);
    // ffn = relu(m @ W1^T + b1) @ W2^T + b2 ; z = LN(ffn + m)
    gemm_tf32<1><<<dim3(8, 2), 256, GEMM_SMEM>>>(pm, W1, b1, pf1, E, 4 * MDIM, MDIM, 1.f);
    gemm_tf32<0><<<dim3(2, 2), 256, GEMM_SMEM>>>(pf1, W2, b2, pf2, E, MDIM, 4 * MDIM, 1.f);
    ln_kernel<<<E, 128>>>(pf2, pm, out);
}

// round 4
// speedup vs baseline: 1.2528x; 1.2073x over previous
#include <cuda_runtime.h>
#include <cstdint>

#define E       256
#define MDIM    512
#define NTOK    50000
#define NPAD    50176       // 392 * 128
#define DDIM    256
#define HEADS   8
#define DH      64
#define INNER   512
#define CHUNK   1024
#define NCHUNK  49
#define NCHUNK2 98          // token-split doubles partial slots
#define NSTEPS  16
#define NTB     784         // NPAD/64 token tiles
#define MB_W    1568        // mask bitword stride (even, >= ceil(50000/32))

// ---------------- scratch (device globals; no allocs allowed) ----------------
__device__ float    g_q   [E * INNER];                  // pre-scaled by dh^-0.5
__device__ uint32_t g_xp  [392 * 8 * 4096];             // packed x (A-frag tf32)
__device__ uint32_t g_wkvp[8 * 8 * 4096];               // packed Wkv (B-frag tf32)
__device__ uint32_t g_K   [HEADS * NTB * 4096];         // packed K tiles (tf32)
__device__ uint32_t g_V   [HEADS * NTB * 4096];         // packed sigma-V tiles (tf32)
__device__ uint32_t g_mbits[E * MB_W];
__device__ int      g_mask_mode;
__device__ float    g_pnum[HEADS * NCHUNK2 * E * DH];
__device__ float    g_pden[HEADS * NCHUNK2 * E];
__device__ float    g_att [E * INNER];
__device__ float    g_t1  [E * MDIM];
__device__ float    g_m   [E * MDIM];
__device__ float    g_f1  [E * 4 * MDIM];
__device__ float    g_f2  [E * MDIM];

// ---------------- helpers ----------------
__device__ __forceinline__ uint32_t f2tf(float x) {
    uint32_t r;
    asm("cvt.rna.tf32.f32 %0, %1;" : "=r"(r) : "f"(x));
    return r;
}
__device__ __forceinline__ void mma8(float (&c)[4], const uint32_t (&a)[4],
                                     uint32_t b0, uint32_t b1) {
    asm volatile(
        "mma.sync.aligned.m16n8k8.row.col.f32.tf32.tf32.f32 "
        "{%0,%1,%2,%3},{%4,%5,%6,%7},{%8,%9},{%0,%1,%2,%3};"
        : "+f"(c[0]), "+f"(c[1]), "+f"(c[2]), "+f"(c[3])
        : "r"(a[0]), "r"(a[1]), "r"(a[2]), "r"(a[3]), "r"(b0), "r"(b1));
}
__device__ __forceinline__ void cp16(uint32_t sm, const void* g) {
    asm volatile("cp.async.cg.shared.global [%0], [%1], 16;" :: "r"(sm), "l"(g));
}
__device__ __forceinline__ void cp8(uint32_t sm, const void* g) {
    asm volatile("cp.async.ca.shared.global [%0], [%1], 8;" :: "r"(sm), "l"(g));
}
__device__ __forceinline__ void cpcommit() { asm volatile("cp.async.commit_group;"); }
template<int N> __device__ __forceinline__ void cpwait() {
    asm volatile("cp.async.wait_group %0;" :: "n"(N));
}

// ---------------- mask dtype sniffer (proven) ----------------
__global__ void detect_mask_kernel(const uint32_t* __restrict__ m) {
    int t = threadIdx.x;
    bool bf = false, by = false, d64 = false;
    for (int i = t; i < 256; i += 32) {
        uint32_t w = m[i];
        if (w == 0x3F803F80u || w == 0x00003F80u) bf = true;
        else if (w == 0x3FF00000u) d64 = true;
        else if (w != 0u && w != 1u && w != 0x3F800000u) by = true;
    }
    bf  = __any_sync(0xFFFFFFFFu, bf);
    by  = __any_sync(0xFFFFFFFFu, by);
    d64 = __any_sync(0xFFFFFFFFu, d64);
    if (t == 0) g_mask_mode = bf ? 2 : (d64 ? 3 : (by ? 1 : 0));
}

__global__ void mask_bits_kernel(const void* __restrict__ mask) {
    int w = blockIdx.x * blockDim.x + threadIdx.x;
    int r = blockIdx.y;
    if (w >= MB_W) return;
    uint32_t bits = 0;
    int n0 = w << 5;
    int mode = g_mask_mode;
    size_t base = (size_t)r * NTOK;
    if (n0 + 32 <= NTOK) {
        if (mode == 1) {
            const uint32_t* p = (const uint32_t*)((const uint8_t*)mask + base + n0);
            #pragma unroll
            for (int k = 0; k < 8; k++) {
                uint32_t u = p[k];
                #pragma unroll
                for (int b = 0; b < 4; b++)
                    bits |= (((u >> (8 * b)) & 0xFFu) ? 1u : 0u) << (k * 4 + b);
            }
        } else if (mode == 2) {
            const uint32_t* p = (const uint32_t*)((const uint16_t*)mask + base + n0);
            #pragma unroll
            for (int k = 0; k < 16; k++) {
                uint32_t u = p[k];
                bits |= ((u & 0xFFFFu) ? 1u : 0u) << (k * 2);
                bits |= ((u >> 16) ? 1u : 0u) << (k * 2 + 1);
            }
        } else if (mode == 3) {
            const uint2* p = (const uint2*)mask + base + n0;
            #pragma unroll
            for (int k = 0; k < 32; k++) {
                uint2 u = p[k];
                bits |= ((u.x | u.y) ? 1u : 0u) << k;
            }
        } else {
            const uint32_t* p = (const uint32_t*)mask + base + n0;
            #pragma unroll
            for (int k = 0; k < 32; k++)
                bits |= (p[k] ? 1u : 0u) << k;
        }
    } else {
        for (int b = 0; b < 32; b++) {
            int nn = n0 + b;
            if (nn >= NTOK) break;
            uint32_t v;
            if (mode == 1)      v = ((const uint8_t*)mask)[base + nn];
            else if (mode == 2) v = ((const uint16_t*)mask)[base + nn];
            else if (mode == 3) { uint2 u = ((const uint2*)mask)[base + nn]; v = u.x | u.y; }
            else                v = ((const uint32_t*)mask)[base + nn];
            bits |= (v ? 1u : 0u) << b;
        }
    }
    g_mbits[r * MB_W + w] = bits;
}

// ---------------- prep: pack x into A-frag tf32 layout ----------------
// element (r,k): word = (Rblk*8+kt)*4096 + ((rb*4+kb)*32 + gg*4 + j)*4 + (hh+2vv)
__global__ void pack_x_kernel(const float* __restrict__ x) {
    int idx = blockIdx.x * 256 + threadIdx.x;     // NPAD*64 = 3,211,264
    int r = idx >> 6, k0 = (idx & 63) << 2;
    float4 v = (r < NTOK) ? *(const float4*)&x[(size_t)r * DDIM + k0]
                          : make_float4(0.f, 0.f, 0.f, 0.f);
    int Rblk = r >> 7, rl = r & 127;
    int rb = rl >> 4, hh = (rl >> 3) & 1, gg = rl & 7;
    int kt = k0 >> 5, kb = (k0 >> 3) & 3, vv = (k0 >> 2) & 1;
    uint32_t base = (uint32_t)((Rblk * 8 + kt) * 4096 + ((rb * 4 + kb) * 32 + gg * 4) * 4
                               + hh + 2 * vv);
    g_xp[base + 0]  = f2tf(v.x);
    g_xp[base + 4]  = f2tf(v.y);
    g_xp[base + 8]  = f2tf(v.z);
    g_xp[base + 12] = f2tf(v.w);
}

// pack Wkv (1024 x 256) into B-frag tf32 layout
// element (n,k): word = (Nblk*8+kt)*4096 + ((nb*4+kb)*32 + gg*4 + j)*2 + s
__global__ void pack_wkv_kernel(const float* __restrict__ Wkv) {
    int idx = blockIdx.x * 256 + threadIdx.x;     // 1024*64 = 65536
    int n = idx >> 6, k0 = (idx & 63) << 2;
    float4 v = *(const float4*)&Wkv[(size_t)n * DDIM + k0];
    int Nblk = n >> 7, nb = (n & 127) >> 3, gg = n & 7;
    int kt = k0 >> 5, kb = (k0 >> 3) & 3, s = (k0 >> 2) & 1;
    uint32_t base = (uint32_t)((Nblk * 8 + kt) * 4096 + ((nb * 4 + kb) * 32 + gg * 4) * 2 + s);
    g_wkvp[base + 0] = f2tf(v.x);
    g_wkvp[base + 2] = f2tf(v.y);
    g_wkvp[base + 4] = f2tf(v.z);
    g_wkvp[base + 6] = f2tf(v.w);
}

// ================= KV GEMM: kv = x @ Wkv^T + bkv, epilogue -> packed gK/gV ===
// BM=128, BN=128, BK=32, 256 thr, 8 warps (2m x 4n), warp 64x32.
// cp.async pre-packed tiles, 3-stage. 2 CTAs/SM.
#define KVG_SMEM (24576 * 4)
__global__ void __launch_bounds__(256, 2)
kv_gemm_kernel(const float* __restrict__ bkv) {
    extern __shared__ uint32_t sm[];
    uint32_t smb = (uint32_t)__cvta_generic_to_shared(sm);
    int bn = blockIdx.x, bmk = blockIdx.y;
    int tid = threadIdx.x, warp = tid >> 5, lane = tid & 31;
    int wm = warp >> 2, wn = warp & 3;
    int g = lane >> 2, j = lane & 3;

    const uint32_t* Asrc = g_xp   + (size_t)bmk * 32768;
    const uint32_t* Bsrc = g_wkvp + (size_t)bn  * 32768;

    auto load = [&](int kt) {
        int st = kt % 3;
        uint32_t da = smb + (st * 8192 + tid * 4) * 4;
        const uint32_t* sa = Asrc + kt * 4096 + tid * 4;
        const uint32_t* sb = Bsrc + kt * 4096 + tid * 4;
        #pragma unroll
        for (int i = 0; i < 4; i++) {
            cp16(da + i * 4096, sa + i * 1024);               // A: 4096 words
            cp16(da + 16384 + i * 4096, sb + i * 1024);       // B: 4096 words
        }
    };

    float acc[4][4][4] = {};
    load(0); cpcommit();
    load(1); cpcommit();

    for (int kt = 0; kt < 8; kt++) {
        if (kt + 2 < 8) cpwait<1>(); else cpwait<0>();
        __syncthreads();
        if (kt + 2 < 8) { load(kt + 2); cpcommit(); }
        const uint32_t* Ab = sm + (kt % 3) * 8192;
        const uint32_t* Bb = Ab + 4096;
        #pragma unroll
        for (int kb = 0; kb < 4; kb++) {
            uint32_t a[4][4];
            #pragma unroll
            for (int mi = 0; mi < 4; mi++) {
                uint4 av = *(const uint4*)&Ab[(((wm * 4 + mi) * 4 + kb) * 32 + lane) * 4];
                a[mi][0] = av.x; a[mi][1] = av.y; a[mi][2] = av.z; a[mi][3] = av.w;
            }
            #pragma unroll
            for (int ni = 0; ni < 4; ni++) {
                uint2 b = *(const uint2*)&Bb[(((wn * 4 + ni) * 4 + kb) * 32 + lane) * 2];
                #pragma unroll
                for (int mi = 0; mi < 4; mi++)
                    mma8(acc[mi][ni], a[mi], b.x, b.y);
            }
        }
    }

    // epilogue: +bias, convert tf32, scatter into packed K or V tiles
    bool isK = (bn * 128 < 512);
    int fb = bn * 128 - (isK ? 0 : 512);
    #pragma unroll
    for (int mi = 0; mi < 4; mi++)
        #pragma unroll
        for (int rh = 0; rh < 2; rh++) {
            int tok = bmk * 128 + wm * 64 + mi * 16 + rh * 8 + g;
            int tb = tok >> 6, t64 = tok & 63;
            #pragma unroll
            for (int ni = 0; ni < 4; ni++)
                #pragma unroll
                for (int qq = 0; qq < 2; qq++) {
                    int cfg = bn * 128 + wn * 32 + ni * 8 + 2 * j + qq;   // global feature
                    int cf  = fb + wn * 32 + ni * 8 + 2 * j + qq;         // within-half
                    int h = cf >> 6, dh = cf & 63;
                    float v = acc[mi][ni][rh * 2 + qq] + bkv[cfg];
                    uint32_t tv = f2tf(v);
                    if (isK) {
                        int nb = t64 >> 3, gg = t64 & 7;
                        g_K[(size_t)(h * NTB + tb) * 4096 +
                            ((nb * 8 + (dh >> 3)) * 32 + gg * 4 + (dh & 3)) * 2 +
                            ((dh >> 2) & 1)] = tv;
                    } else {
                        int ktb = t64 >> 3, w = t64 & 7;
                        g_V[(size_t)(h * NTB + tb) * 4096 +
                            (((dh >> 3) * 8 + ktb) * 32 + (dh & 7) * 4 + (w >> 1)) * 2 +
                            (w & 1)] = tv;
                    }
                }
        }
}

// ================= attention =================
// Block: 128 q-rows (qh half) x 1024-token chunk x head. 8 warps = 4 row x 2 tok.
// cp.async packed K/V tiles; exp->tf32 in place; partials to slot c2 = 2c+wt.
#define ATTN_SMEM (25088 * 4)
__global__ void __launch_bounds__(256, 2) attn_kernel() {
    extern __shared__ uint32_t smu[];
    uint32_t smb = (uint32_t)__cvta_generic_to_shared(smu);
    uint32_t* qp = smu;                       // 8192 words (128 rows packed)
    int c = blockIdx.x, h = blockIdx.y, qh = blockIdx.z;
    int tid = threadIdx.x, warp = tid >> 5, lane = tid & 31;
    int g = lane >> 2, j = lane & 3;
    int wr = warp >> 1, wt = warp & 1;
    int r0 = wr * 32;

    // ---- pack q rows [qh*128, qh*128+128) for this head ----
    #pragma unroll
    for (int p = 0; p < 8; p++) {
        int idx = p * 256 + tid, r = idx >> 4, cc = (idx & 15) * 4;
        float4 v = *(const float4*)&g_q[(size_t)(qh * 128 + r) * INNER + h * DH + cc];
        int rb = r >> 4, hh = (r >> 3) & 1, gg = r & 7;
        int kk = cc >> 3, vv = (cc >> 2) & 1;
        uint32_t base = (uint32_t)(((rb * 8 + kk) * 32 + gg * 4) * 4 + hh + 2 * vv);
        qp[base + 0]  = f2tf(v.x);
        qp[base + 4]  = f2tf(v.y);
        qp[base + 8]  = f2tf(v.z);
        qp[base + 12] = f2tf(v.w);
    }

    auto load = [&](int s) {
        int buf = s & 1;
        int tb = c * 16 + s;
        uint32_t ko = 8192 + buf * 8448;
        const uint32_t* Ks = g_K + (size_t)(h * NTB + tb) * 4096 + tid * 4;
        const uint32_t* Vs = g_V + (size_t)(h * NTB + tb) * 4096 + tid * 4;
        uint32_t dk = smb + (ko + tid * 4) * 4;
        #pragma unroll
        for (int i = 0; i < 4; i++) {
            cp16(dk + i * 4096, Ks + i * 1024);
            cp16(dk + 16384 + i * 4096, Vs + i * 1024);
        }
        if (tid < 128) {
            int w0 = c * 32 + s * 2;
            cp8(smb + (ko + 8192 + tid * 2) * 4,
                &g_mbits[(size_t)(qh * 128 + tid) * MB_W + w0]);
        }
    };

    float acc[2][8][4] = {};
    float den[2][2] = {};

    load(0); cpcommit();

    #pragma unroll 1
    for (int s = 0; s < NSTEPS; s++) {
        cpwait<0>();
        __syncthreads();
        if (s + 1 < NSTEPS) { load(s + 1); cpcommit(); }

        int buf = s & 1;
        const uint32_t* kb_ = smu + 8192 + buf * 8448;
        const uint32_t* vb_ = kb_ + 4096;
        const uint32_t* mw  = kb_ + 8192;

        // ---- QK^T : warp wt covers tokens [32wt, 32wt+32) ----
        float S[2][4][4] = {};
        #pragma unroll
        for (int kk = 0; kk < 8; kk++) {
            uint4 av0 = *(const uint4*)&qp[(((2 * wr + 0) * 8 + kk) * 32 + lane) * 4];
            uint4 av1 = *(const uint4*)&qp[(((2 * wr + 1) * 8 + kk) * 32 + lane) * 4];
            uint32_t a0[4] = {av0.x, av0.y, av0.z, av0.w};
            uint32_t a1[4] = {av1.x, av1.y, av1.z, av1.w};
            #pragma unroll
            for (int ni = 0; ni < 4; ni++) {
                uint2 b = *(const uint2*)&kb_[(((4 * wt + ni) * 8 + kk) * 32 + lane) * 2];
                mma8(S[0][ni], a0, b.x, b.y);
                mma8(S[1][ni], a1, b.x, b.y);
            }
        }

        // ---- mask + exp -> tf32 P in place ----
        uint32_t mk[2][2];
        #pragma unroll
        for (int mi = 0; mi < 2; mi++) {
            mk[mi][0] = mw[(r0 + mi * 16 + g) * 2 + wt];
            mk[mi][1] = mw[(r0 + mi * 16 + 8 + g) * 2 + wt];
        }
        #pragma unroll
        for (int mi = 0; mi < 2; mi++)
            #pragma unroll
            for (int ni = 0; ni < 4; ni++)
                #pragma unroll
                for (int q = 0; q < 4; q++) {
                    int rh = q >> 1;
                    int colb = ni * 8 + 2 * j + (q & 1);
                    float p = ((mk[mi][rh] >> colb) & 1u) ? __expf(S[mi][ni][q]) : 0.f;
                    den[mi][rh] += p;
                    S[mi][ni][q] = __uint_as_float(f2tf(p));
                }

        // ---- P @ V (sigma rename: C-frag == A-frag) ----
        #pragma unroll
        for (int kt = 0; kt < 4; kt++) {
            uint32_t a0[4] = {__float_as_uint(S[0][kt][0]), __float_as_uint(S[0][kt][2]),
                              __float_as_uint(S[0][kt][1]), __float_as_uint(S[0][kt][3])};
            uint32_t a1[4] = {__float_as_uint(S[1][kt][0]), __float_as_uint(S[1][kt][2]),
                              __float_as_uint(S[1][kt][1]), __float_as_uint(S[1][kt][3])};
            #pragma unroll
            for (int nj = 0; nj < 8; nj++) {
                uint2 b = *(const uint2*)&vb_[((nj * 8 + 4 * wt + kt) * 32 + lane) * 2];
                mma8(acc[0][nj], a0, b.x, b.y);
                mma8(acc[1][nj], a1, b.x, b.y);
            }
        }
    }

    // ---- write partials to slot c2 = 2c + wt ----
    int c2 = c * 2 + wt;
    size_t pb = (size_t)(h * NCHUNK2 + c2) * E + qh * 128;
    #pragma unroll
    for (int mi = 0; mi < 2; mi++)
        #pragma unroll
        for (int rh = 0; rh < 2; rh++) {
            float dsum = den[mi][rh];
            dsum += __shfl_xor_sync(0xFFFFFFFFu, dsum, 1);
            dsum += __shfl_xor_sync(0xFFFFFFFFu, dsum, 2);
            if (j == 0) g_pden[pb + r0 + mi * 16 + rh * 8 + g] = dsum;
        }
    #pragma unroll
    for (int mi = 0; mi < 2; mi++)
        #pragma unroll
        for (int nj = 0; nj < 8; nj++)
            #pragma unroll
            for (int q = 0; q < 4; q++) {
                int r = r0 + mi * 16 + g + ((q >= 2) ? 8 : 0);
                int col = nj * 8 + 2 * j + (q & 1);
                g_pnum[(pb + r) * DH + col] = acc[mi][nj][q];
            }
}

// ---------------- combine partials: att = num/den ----------------
__global__ void combine_kernel() {
    int idx = blockIdx.x * 256 + threadIdx.x;    // 131072
    int i = idx >> 9, col = idx & 511;
    int h = col >> 6, t = col & 63;
    float num = 0.f, dsum = 0.f;
    #pragma unroll 7
    for (int c = 0; c < NCHUNK2; c++) {
        size_t base = (size_t)(h * NCHUNK2 + c) * E + i;
        num  += g_pnum[base * DH + t];
        dsum += g_pden[base];
    }
    g_att[i * INNER + col] = num / dsum;
}

// ================= small tf32 GEMM (proven R3 path) =================
#define GEMM_SMEM (24576 * 4)
template <int ACT>
__global__ void __launch_bounds__(256, 1)
gemm_tf32(const float* __restrict__ A, const float* __restrict__ B,
          const float* __restrict__ bias, float* __restrict__ C,
          int Md, int Nd, int Kd, float alpha) {
    extern __shared__ uint32_t smg[];
    uint32_t* Ap = smg;
    uint32_t* Bp = smg + 8192;
    int bm = blockIdx.y * 128, bn = blockIdx.x * 256;
    int tid = threadIdx.x, warp = tid >> 5, lane = tid & 31;
    int g = lane >> 2, j = lane & 3;
    int wm = warp >> 2, wn = warp & 3;

    float4 aR[4], bR[8];
    auto ldg = [&](int kt) {
        int k0 = kt * 32;
        #pragma unroll
        for (int p = 0; p < 4; p++) {
            int idx = p * 256 + tid, r = idx >> 3, c4 = idx & 7;
            int gr = bm + r;
            aR[p] = (gr < Md) ? *(const float4*)&A[(size_t)gr * Kd + k0 + c4 * 4]
                              : make_float4(0.f, 0.f, 0.f, 0.f);
        }
        #pragma unroll
        for (int p = 0; p < 8; p++) {
            int idx = p * 256 + tid, r = idx >> 3, c4 = idx & 7;
            bR[p] = *(const float4*)&B[(size_t)(bn + r) * Kd + k0 + c4 * 4];
        }
    };
    auto sts = [&](int buf) {
        uint32_t* Ad = Ap + buf * 4096;
        uint32_t* Bd = Bp + buf * 8192;
        #pragma unroll
        for (int p = 0; p < 4; p++) {
            int idx = p * 256 + tid, r = idx >> 3, cc = (idx & 7) * 4;
            int rb = r >> 4, rr = r & 15, hh = rr >> 3, gg = rr & 7;
            int kb = cc >> 3, vv = (cc & 7) >> 2;
            uint32_t base = (uint32_t)(((rb * 4 + kb) * 32 + gg * 4) * 4 + (hh + 2 * vv));
            Ad[base + 0]  = f2tf(aR[p].x);
            Ad[base + 4]  = f2tf(aR[p].y);
            Ad[base + 8]  = f2tf(aR[p].z);
            Ad[base + 12] = f2tf(aR[p].w);
        }
        #pragma unroll
        for (int p = 0; p < 8; p++) {
            int idx = p * 256 + tid, r = idx >> 3, cc = (idx & 7) * 4;
            int nb = r >> 3, gg = r & 7, kb = cc >> 3, s = (cc & 7) >> 2;
            uint32_t base = (uint32_t)(((nb * 4 + kb) * 32 + gg * 4) * 2 + s);
            Bd[base + 0] = f2tf(bR[p].x);
            Bd[base + 2] = f2tf(bR[p].y);
            Bd[base + 4] = f2tf(bR[p].z);
            Bd[base + 6] = f2tf(bR[p].w);
        }
    };

    float acc[4][8][4] = {};
    int nt = Kd >> 5;
    ldg(0); sts(0); __syncthreads();
    for (int kt = 0; kt < nt; kt++) {
        if (kt + 1 < nt) ldg(kt + 1);
        const uint32_t* Ab = Ap + (kt & 1) * 4096;
        const uint32_t* Bb = Bp + (kt & 1) * 8192;
        #pragma unroll
        for (int kb = 0; kb < 4; kb++) {
            uint32_t a[4][4];
            #pragma unroll
            for (int mi = 0; mi < 4; mi++) {
                uint4 av = *(const uint4*)&Ab[(((wm * 4 + mi) * 4 + kb) * 32 + lane) * 4];
                a[mi][0] = av.x; a[mi][1] = av.y; a[mi][2] = av.z; a[mi][3] = av.w;
            }
            #pragma unroll
            for (int ni = 0; ni < 8; ni++) {
                uint2 b = *(const uint2*)&Bb[(((wn * 8 + ni) * 4 + kb) * 32 + lane) * 2];
                #pragma unroll
                for (int mi = 0; mi < 4; mi++)
                    mma8(acc[mi][ni], a[mi], b.x, b.y);
            }
        }
        if (kt + 1 < nt) { sts((kt + 1) & 1); __syncthreads(); }
    }
    #pragma unroll
    for (int mi = 0; mi < 4; mi++)
        #pragma unroll
        for (int ni = 0; ni < 8; ni++)
            #pragma unroll
            for (int rh = 0; rh < 2; rh++) {
                int r = bm + wm * 64 + mi * 16 + rh * 8 + g;
                if (r < Md) {
                    int cb = bn + wn * 64 + ni * 8 + 2 * j;
                    float v0 = acc[mi][ni][rh * 2 + 0] * alpha + (bias ? bias[cb] : 0.f);
                    float v1 = acc[mi][ni][rh * 2 + 1] * alpha + (bias ? bias[cb + 1] : 0.f);
                    if (ACT) { v0 = fmaxf(v0, 0.f); v1 = fmaxf(v1, 0.f); }
                    *(float2*)&C[(size_t)r * Nd + cb] = make_float2(v0, v1);
                }
            }
}

// ---------------- residual + LayerNorm over 512 cols ----------------
__global__ void ln_kernel(const float* __restrict__ X, const float* __restrict__ R,
                          float* __restrict__ out) {
    int row = blockIdx.x, tid = threadIdx.x;
    __shared__ float sh1[4], sh2[4];
    float4 x = ((const float4*)X)[row * 128 + tid];
    float4 rr = ((const float4*)R)[row * 128 + tid];
    float v0 = x.x + rr.x, v1 = x.y + rr.y, v2 = x.z + rr.z, v3 = x.w + rr.w;
    float s = v0 + v1 + v2 + v3;
    #pragma unroll
    for (int o = 16; o; o >>= 1) s += __shfl_xor_sync(0xFFFFFFFFu, s, o);
    if ((tid & 31) == 0) sh1[tid >> 5] = s;
    __syncthreads();
    float mu = (sh1[0] + sh1[1] + sh1[2] + sh1[3]) * (1.f / 512.f);
    float d0 = v0 - mu, d1 = v1 - mu, d2 = v2 - mu, d3 = v3 - mu;
    float ss = d0 * d0 + d1 * d1 + d2 * d2 + d3 * d3;
    #pragma unroll
    for (int o = 16; o; o >>= 1) ss += __shfl_xor_sync(0xFFFFFFFFu, ss, o);
    if ((tid & 31) == 0) sh2[tid >> 5] = ss;
    __syncthreads();
    float var = (sh2[0] + sh2[1] + sh2[2] + sh2[3]) * (1.f / 512.f);
    float inv = rsqrtf(var + 1e-5f);
    ((float4*)out)[row * 128 + tid] = make_float4(d0 * inv, d1 * inv, d2 * inv, d3 * inv);
}

// ---------------- launcher ----------------
extern "C" void kernel_launch(void* const* d_in, const int* in_sizes, int n_in,
                              void* d_out, int out_size) {
    const float* M    = (const float*)d_in[0];
    const float* x    = (const float*)d_in[1];
    const void*  mask = d_in[2];
    const float* Wq   = (const float*)d_in[3];
    const float* Wkv  = (const float*)d_in[4];
    const float* bkv  = (const float*)d_in[5];
    const float* Wo   = (const float*)d_in[6];
    const float* bo   = (const float*)d_in[7];
    const float* W1   = (const float*)d_in[8];
    const float* b1   = (const float*)d_in[9];
    const float* W2   = (const float*)d_in[10];
    const float* b2   = (const float*)d_in[11];
    float* out = (float*)d_out;

    float *pq, *patt, *pt1, *pm, *pf1, *pf2;
    cudaGetSymbolAddress((void**)&pq,   g_q);
    cudaGetSymbolAddress((void**)&patt, g_att);
    cudaGetSymbolAddress((void**)&pt1,  g_t1);
    cudaGetSymbolAddress((void**)&pm,   g_m);
    cudaGetSymbolAddress((void**)&pf1,  g_f1);
    cudaGetSymbolAddress((void**)&pf2,  g_f2);

    cudaFuncSetAttribute(kv_gemm_kernel, cudaFuncAttributeMaxDynamicSharedMemorySize, KVG_SMEM);
    cudaFuncSetAttribute(attn_kernel,    cudaFuncAttributeMaxDynamicSharedMemorySize, ATTN_SMEM);
    cudaFuncSetAttribute(gemm_tf32<0>,   cudaFuncAttributeMaxDynamicSharedMemorySize, GEMM_SMEM);
    cudaFuncSetAttribute(gemm_tf32<1>,   cudaFuncAttributeMaxDynamicSharedMemorySize, GEMM_SMEM);

    detect_mask_kernel<<<1, 32>>>((const uint32_t*)mask);
    mask_bits_kernel<<<dim3(7, E), 256>>>(mask);
    pack_x_kernel<<<12544, 256>>>(x);
    pack_wkv_kernel<<<256, 256>>>(Wkv);

    // q = (M @ Wq^T) * dh^-0.5
    gemm_tf32<0><<<dim3(2, 2), 256, GEMM_SMEM>>>(M, Wq, nullptr, pq, E, INNER, MDIM, 0.125f);
    // kv = x @ Wkv^T + bkv -> packed gK / gV
    kv_gemm_kernel<<<dim3(8, 392), 256, KVG_SMEM>>>(bkv);

    attn_kernel<<<dim3(NCHUNK, HEADS, 2), 256, ATTN_SMEM>>>();
    combine_kernel<<<512, 256>>>();

    // out = att @ Wo^T + bo ; m = LN(out + M)
    gemm_tf32<0><<<dim3(2, 2), 256, GEMM_SMEM>>>(patt, Wo, bo, pt1, E, MDIM, INNER, 1.f);
    ln_kernel<<<E, 128>>>(pt1, M, pm);
    // ffn = relu(m @ W1^T + b1) @ W2^T + b2 ; z = LN(ffn + m)
    gemm_tf32<1><<<dim3(8, 2), 256, GEMM_SMEM>>>(pm, W1, b1, pf1, E, 4 * MDIM, MDIM, 1.f);
    gemm_tf32<0><<<dim3(2, 2), 256, GEMM_SMEM>>>(pf1, W2, b2, pf2, E, MDIM, 4 * MDIM, 1.f);
    ln_kernel<<<E, 128>>>(pf2, pm, out);
}